// round 14
// baseline (speedup 1.0000x reference)
#include <cuda_runtime.h>
#include <cuda_fp16.h>
#include <cstdint>

// Problem constants
#define BATCH 32
#define NPTS  8192
#define DIM   128
#define LAM   0.01f

// split-K SYRK config
#define SPLITS 8
#define KC     (NPTS / SPLITS)   // 1024 k-rows per CTA
#define KT     32                // k-rows per smem tile
#define TILES  (KC / KT)         // 32
#define SD     136               // smem row stride (floats)
#define PIPE   4                 // raw ring depth
#define TILEF  (KT * SD)         // floats per tile buffer (4352)

// Static device scratch (fp16 partials: 8 MB)
__device__ __half g_covp[SPLITS][BATCH][DIM][DIM];
__device__ float  g_sums[SPLITS][BATCH][DIM];
__device__ float  g_keyp[SPLITS][BATCH][DIM];      // exact fp32 dot(col_d, col_0)

// ---------------------------------------------------------------------------
// tf32 warp MMA m16n8k8 — fragment layout VERIFIED (R7/R10/R13 pass)
// ---------------------------------------------------------------------------
__device__ __forceinline__ void mma_tf32(float c[4],
                                         uint32_t a0, uint32_t a1, uint32_t a2, uint32_t a3,
                                         uint32_t b0, uint32_t b1) {
    asm volatile(
        "mma.sync.aligned.m16n8k8.row.col.f32.tf32.tf32.f32 "
        "{%0,%1,%2,%3}, {%4,%5,%6,%7}, {%8,%9}, {%0,%1,%2,%3};"
        : "+f"(c[0]), "+f"(c[1]), "+f"(c[2]), "+f"(c[3])
        : "r"(a0), "r"(a1), "r"(a2), "r"(a3), "r"(b0), "r"(b1));
}

__device__ __forceinline__ uint32_t to_tf32(float v) {
    uint32_t u;
    asm("cvt.rn.tf32.f32 %0, %1;" : "=r"(u) : "f"(v));
    return u;
}

__device__ __forceinline__ uint32_t smem_u32(const void* p) {
    uint32_t a;
    asm("{ .reg .u64 t; cvta.to.shared.u64 t, %1; cvt.u32.u64 %0, t; }"
        : "=r"(a) : "l"(p));
    return a;
}

#define CP_ASYNC16(saddr, gptr) \
    asm volatile("cp.async.cg.shared.global [%0], [%1], 16;" \
        :: "r"(saddr), "l"(gptr) : "memory")
#define CP_COMMIT() asm volatile("cp.async.commit_group;" ::: "memory")
#define CP_WAIT2()  asm volatile("cp.async.wait_group 2;" ::: "memory")

// ---------------------------------------------------------------------------
// Kernel 1: split-K SYRK. cp.async raw ring -> per-thread private convert
// (exact colsum/key accumulate + cvt.rn) -> tf32 double buffer -> MMA.
// grid = BATCH*SPLITS, 256 threads (8 warps), warp tile 32x64, 2 CTAs/SM.
// ---------------------------------------------------------------------------
__global__ __launch_bounds__(256, 2)
void syrk_mma_kernel(const float* __restrict__ x) {
    extern __shared__ float sm[];
    float* rawR  = sm;                        // PIPE x TILEF (raw fp32)
    float* tfR   = sm + PIPE * TILEF;         // 2 x TILEF (tf32 bits)
    float* sCsum = sm + (PIPE + 2) * TILEF;   // 256 float4
    float* sKsum = sCsum + 1024;
    const uint32_t sbRaw = smem_u32(rawR);

    const int bid = blockIdx.x;
    const int b = bid / SPLITS;
    const int s = bid % SPLITS;
    const float* __restrict__ xb = x + ((size_t)b * NPTS + (size_t)s * KC) * DIM;

    const int tid  = threadIdx.x;
    const int lane = tid & 31;
    const int wid  = tid >> 5;
    const int g    = lane >> 2;
    const int t4   = lane & 3;
    const int wm   = (wid & 3) * 32;
    const int wn   = (wid >> 2) * 64;
    const int d4   = tid & 31;           // column group (4 cols)
    const int krow = tid >> 5;           // base k-row (0..7)

    float4 csum = make_float4(0.f, 0.f, 0.f, 0.f);
    float4 ksum = make_float4(0.f, 0.f, 0.f, 0.f);
    float acc[2][8][4];
#pragma unroll
    for (int mt = 0; mt < 2; ++mt)
#pragma unroll
        for (int nt = 0; nt < 8; ++nt)
#pragma unroll
            for (int q = 0; q < 4; ++q) acc[mt][nt][q] = 0.f;

    // ---- prologue: issue cp.async for tiles 0..PIPE-2 ----
#pragma unroll
    for (int t = 0; t < PIPE - 1; ++t) {
        const float* gt = xb + (size_t)t * KT * DIM;
        const uint32_t sbuf = sbRaw + (uint32_t)t * (TILEF * 4);
#pragma unroll
        for (int r = 0; r < 4; ++r) {
            const int row = krow + 8 * r;
            CP_ASYNC16(sbuf + (uint32_t)(row * SD + d4 * 4) * 4,
                       gt + row * DIM + d4 * 4);
        }
        CP_COMMIT();
    }

    // ---- main loop ----
    for (int t = 0; t < TILES; ++t) {
        CP_WAIT2();   // own copies of tile t complete (thread-private rows)

        // private convert stage: raw -> colsum/keys -> cvt.rn -> tf32 buffer
        const float* rb = rawR + (size_t)(t & (PIPE - 1)) * TILEF;
        float* tb = tfR + (size_t)(t & 1) * TILEF;
#pragma unroll
        for (int r = 0; r < 4; ++r) {
            const int k = krow + 8 * r;
            const float4 v = *(const float4*)&rb[k * SD + d4 * 4];
            const float x0 = __shfl_sync(0xffffffffu, v.x, (d4 == 0) ? lane : 0, 32);
            // NOTE: x0 must be element (k,0); thread with d4==0 holds it.
            csum.x += v.x; csum.y += v.y; csum.z += v.z; csum.w += v.w;
            const float xk0 = __shfl_sync(0xffffffffu, v.x, 0, 32) * 0.f + x0; // keep x0
            ksum.x = fmaf(v.x, xk0, ksum.x);
            ksum.y = fmaf(v.y, xk0, ksum.y);
            ksum.z = fmaf(v.z, xk0, ksum.z);
            ksum.w = fmaf(v.w, xk0, ksum.w);
            uint4 uv = make_uint4(to_tf32(v.x), to_tf32(v.y),
                                  to_tf32(v.z), to_tf32(v.w));
            *(uint4*)&tb[k * SD + d4 * 4] = uv;
        }

        // issue cp.async for tile t+PIPE-1 (commit always)
        if (t + PIPE - 1 < TILES) {
            const float* gt = xb + (size_t)(t + PIPE - 1) * KT * DIM;
            const uint32_t sbuf = sbRaw +
                (uint32_t)((t + PIPE - 1) & (PIPE - 1)) * (TILEF * 4);
#pragma unroll
            for (int r = 0; r < 4; ++r) {
                const int row = krow + 8 * r;
                CP_ASYNC16(sbuf + (uint32_t)(row * SD + d4 * 4) * 4,
                           gt + row * DIM + d4 * 4);
            }
        }
        CP_COMMIT();

        __syncthreads();   // tf32 tile t visible; frag LDS of t-1 complete

        // 4 k-steps of 8 over tf32 buffer (verified fragment pattern)
#pragma unroll
        for (int ks = 0; ks < 4; ++ks) {
            const float* base = &tb[(ks * 8 + t4) * SD];

            uint32_t bf[8][2];
#pragma unroll
            for (int nt = 0; nt < 8; ++nt) {
                bf[nt][0] = __float_as_uint(base[wn + nt * 8 + g]);
                bf[nt][1] = __float_as_uint(base[4 * SD + wn + nt * 8 + g]);
            }
#pragma unroll
            for (int mt = 0; mt < 2; ++mt) {
                const int m0 = wm + mt * 16;
                uint32_t a0 = __float_as_uint(base[m0 + g]);
                uint32_t a1 = __float_as_uint(base[m0 + g + 8]);
                uint32_t a2 = __float_as_uint(base[4 * SD + m0 + g]);
                uint32_t a3 = __float_as_uint(base[4 * SD + m0 + g + 8]);
#pragma unroll
                for (int nt = 0; nt < 8; ++nt)
                    mma_tf32(acc[mt][nt], a0, a1, a2, a3, bf[nt][0], bf[nt][1]);
            }
        }
    }

    // ---- column-sum + key reductions ----
    ((float4*)sCsum)[tid] = csum;
    ((float4*)sKsum)[tid] = ksum;
    __syncthreads();
    if (tid < 32) {
        float4 a = ((float4*)sCsum)[tid];
        float4 k = ((float4*)sKsum)[tid];
#pragma unroll
        for (int w = 1; w < 8; ++w) {
            float4 u = ((float4*)sCsum)[tid + 32 * w];
            a.x += u.x; a.y += u.y; a.z += u.z; a.w += u.w;
            float4 q = ((float4*)sKsum)[tid + 32 * w];
            k.x += q.x; k.y += q.y; k.z += q.z; k.w += q.w;
        }
        ((float4*)&g_sums[s][b][0])[tid] = a;
        ((float4*)&g_keyp[s][b][0])[tid] = k;
    }

    // ---- write partial cov (fp16) ----
    __half* outp = &g_covp[s][b][0][0];
#pragma unroll
    for (int mt = 0; mt < 2; ++mt) {
#pragma unroll
        for (int nt = 0; nt < 8; ++nt) {
            const int row = wm + mt * 16 + g;
            const int col = wn + nt * 8 + t4 * 2;
            *(__half2*)&outp[(size_t)row * DIM + col] =
                __float22half2_rn(make_float2(acc[mt][nt][0], acc[mt][nt][1]));
            *(__half2*)&outp[(size_t)(row + 8) * DIM + col] =
                __float22half2_rn(make_float2(acc[mt][nt][2], acc[mt][nt][3]));
        }
    }
}

// ---------------------------------------------------------------------------
// Kernel 2: fused finalize + scatter-sort (R13-proven, unchanged).
// ---------------------------------------------------------------------------
__global__ __launch_bounds__(256)
void finalize_scatter_kernel(float* __restrict__ out) {
    __shared__ float ssum[DIM];
    __shared__ float skey[DIM];
    __shared__ int   srank[16];

    const int b    = blockIdx.x >> 3;
    const int slab = blockIdx.x & 7;
    const int tid  = threadIdx.x;

    if (tid < DIM) {
        float sd = 0.f, kd = 0.f;
#pragma unroll
        for (int sp = 0; sp < SPLITS; ++sp) {
            sd += g_sums[sp][b][tid];
            kd += g_keyp[sp][b][tid];
        }
        ssum[tid] = sd;
        skey[tid] = kd;
    }
    __syncthreads();

    const float inv_n   = 1.0f / NPTS;
    const float inv_nm1 = 1.0f / (NPTS - 1);
    const float m0 = ssum[0] * inv_n;

    if (tid < DIM) {
        const float md = ssum[tid] * inv_n;
        float kv = (skey[tid] - (float)NPTS * md * m0) * inv_nm1;
        if (tid == 0) kv += LAM;
        skey[tid] = kv;
    }
    __syncthreads();

    if (tid < 16) {
        const int row = slab * 16 + tid;
        const float ki = skey[row];
        int r = 0;
        for (int j = 0; j < DIM; ++j) {
            const float kj = skey[j];
            if (kj < ki || (kj == ki && j < row)) ++r;
        }
        srank[tid] = r;
    }
    __syncthreads();

    float* ob = out + (size_t)b * (DIM * DIM);

#pragma unroll
    for (int r = 0; r < 2; ++r) {
        const int i = tid + 256 * r;
        const int dl = i >> 5;
        const int dd = slab * 16 + dl;
        const int e4 = i & 31;

        float4 acc = make_float4(0.f, 0.f, 0.f, 0.f);
#pragma unroll
        for (int sp = 0; sp < SPLITS; ++sp) {
            const __half2* p = (const __half2*)&g_covp[sp][b][dd][e4 * 4];
            float2 lo = __half22float2(p[0]);
            float2 hi = __half22float2(p[1]);
            acc.x += lo.x; acc.y += lo.y; acc.z += hi.x; acc.w += hi.y;
        }
        const float md = ssum[dd] * inv_n;
        const float4 se = *(const float4*)&ssum[e4 * 4];
        float4 o;
        o.x = (acc.x - (float)NPTS * md * (se.x * inv_n)) * inv_nm1;
        o.y = (acc.y - (float)NPTS * md * (se.y * inv_n)) * inv_nm1;
        o.z = (acc.z - (float)NPTS * md * (se.z * inv_n)) * inv_nm1;
        o.w = (acc.w - (float)NPTS * md * (se.w * inv_n)) * inv_nm1;
        const int e0 = e4 * 4;
        if (dd >= e0 && dd < e0 + 4) {
            if (dd == e0)     o.x += LAM;
            if (dd == e0 + 1) o.y += LAM;
            if (dd == e0 + 2) o.z += LAM;
            if (dd == e0 + 3) o.w += LAM;
        }
        if (e4 == 0) o.x = skey[dd];

        *(float4*)&ob[(size_t)srank[dl] * DIM + e4 * 4] = o;
    }
}

// ---------------------------------------------------------------------------
extern "C" void kernel_launch(void* const* d_in, const int* in_sizes, int n_in,
                              void* d_out, int out_size) {
    const float* x = (const float*)d_in[0];
    float* out = (float*)d_out;

    const int SMEM1 = ((PIPE + 2) * TILEF + 2048) * 4;   // 112,640 B
    cudaFuncSetAttribute(syrk_mma_kernel,
                         cudaFuncAttributeMaxDynamicSharedMemorySize, SMEM1);

    syrk_mma_kernel<<<BATCH * SPLITS, 256, SMEM1>>>(x);
    finalize_scatter_kernel<<<BATCH * 8, 256>>>(out);
}

// round 15
// speedup vs baseline: 1.3378x; 1.3378x over previous
#include <cuda_runtime.h>
#include <cuda_fp16.h>
#include <cstdint>

// Problem constants
#define BATCH 32
#define NPTS  8192
#define DIM   128
#define LAM   0.01f

// split-K SYRK config
#define SPLITS 8
#define KC     (NPTS / SPLITS)   // 1024 k-rows per CTA
#define KT     32                // k-rows per smem tile (16 bf16x2 pair-rows)
#define TILES  (KC / KT)         // 32
#define SD2    136               // packed smem row stride (uint32); 136%32==8 -> bank-injective

// Static device scratch (fp16 partials: 8 MB)
__device__ __half g_covp[SPLITS][BATCH][DIM][DIM];
__device__ float  g_sums[SPLITS][BATCH][DIM];
__device__ float  g_keyp[SPLITS][BATCH][DIM];      // exact fp32 dot(col_d, col_0)

// ---------------------------------------------------------------------------
// bf16 warp MMA m16n8k16 (full-rate HMMA.16816, compute_103-safe, sm_80+).
// A/B fragments read the SAME packed buffer -> any k-pair packing convention
// cancels in the SYRK sum; only the row-group order (g / g+8) matters.
// ---------------------------------------------------------------------------
__device__ __forceinline__ void mma_bf16(float c[4],
                                         uint32_t a0, uint32_t a1, uint32_t a2, uint32_t a3,
                                         uint32_t b0, uint32_t b1) {
    asm volatile(
        "mma.sync.aligned.m16n8k16.row.col.f32.bf16.bf16.f32 "
        "{%0,%1,%2,%3}, {%4,%5,%6,%7}, {%8,%9}, {%0,%1,%2,%3};"
        : "+f"(c[0]), "+f"(c[1]), "+f"(c[2]), "+f"(c[3])
        : "r"(a0), "r"(a1), "r"(a2), "r"(a3), "r"(b0), "r"(b1));
}

__device__ __forceinline__ uint32_t pack_bf16x2(float lo, float hi) {
    uint32_t u;
    asm("cvt.rn.bf16x2.f32 %0, %1, %2;" : "=r"(u) : "f"(hi), "f"(lo));
    return u;
}

// ---------------------------------------------------------------------------
// Kernel 1: split-K SYRK via bf16 mma.sync, 64x64 warp tiles.
// grid = BATCH*SPLITS, 128 threads (4 warps), 2 CTAs/SM.
// LDG row-pairs -> exact colsum/key accumulate -> pack bf16x2 -> STS.
// ---------------------------------------------------------------------------
__global__ __launch_bounds__(128, 2)
void syrk_mma_kernel(const float* __restrict__ x) {
    __shared__ uint32_t sP[2][(KT / 2) * SD2];   // 2 x 8704 B packed tiles
    __shared__ float4 sCsum[128];
    __shared__ float4 sKsum[128];

    const int bid = blockIdx.x;
    const int b = bid / SPLITS;
    const int s = bid % SPLITS;
    const float* __restrict__ xb = x + ((size_t)b * NPTS + (size_t)s * KC) * DIM;

    const int tid  = threadIdx.x;
    const int lane = tid & 31;
    const int wid  = tid >> 5;           // 0..3
    const int g    = lane >> 2;          // 0..7
    const int t4   = lane & 3;           // 0..3
    const int wm   = (wid & 1) * 64;     // warp M offset
    const int wn   = (wid >> 1) * 64;    // warp N offset
    const int d4   = tid & 31;           // fixed column group (4 cols)
    const int krow = tid >> 5;           // 0..3 base pair-row

    float4 csum = make_float4(0.f, 0.f, 0.f, 0.f);
    float4 ksum = make_float4(0.f, 0.f, 0.f, 0.f);
    float acc[4][8][4];
#pragma unroll
    for (int mt = 0; mt < 4; ++mt)
#pragma unroll
        for (int nt = 0; nt < 8; ++nt)
#pragma unroll
            for (int q = 0; q < 4; ++q) acc[mt][nt][q] = 0.f;

    float4 pv[8];   // 4 pair-rows x 2 rows x 4 cols per thread per tile

    // ---- prologue: load tile 0, accumulate, pack, store ----
    {
        const float4* src = (const float4*)xb;
#pragma unroll
        for (int r = 0; r < 4; ++r) {
            pv[2 * r]     = __ldg(src + (2 * krow + 8 * r) * 32 + d4);
            pv[2 * r + 1] = __ldg(src + (2 * krow + 8 * r + 1) * 32 + d4);
        }
#pragma unroll
        for (int r = 0; r < 4; ++r) {
            const float4 v0 = pv[2 * r], v1 = pv[2 * r + 1];
            const float x00 = __shfl_sync(0xffffffffu, v0.x, 0);
            const float x01 = __shfl_sync(0xffffffffu, v1.x, 0);
            csum.x += v0.x + v1.x; csum.y += v0.y + v1.y;
            csum.z += v0.z + v1.z; csum.w += v0.w + v1.w;
            ksum.x = fmaf(v0.x, x00, fmaf(v1.x, x01, ksum.x));
            ksum.y = fmaf(v0.y, x00, fmaf(v1.y, x01, ksum.y));
            ksum.z = fmaf(v0.z, x00, fmaf(v1.z, x01, ksum.z));
            ksum.w = fmaf(v0.w, x00, fmaf(v1.w, x01, ksum.w));
            const int kp = krow + 4 * r;
            uint4 uv = make_uint4(pack_bf16x2(v0.x, v1.x), pack_bf16x2(v0.y, v1.y),
                                  pack_bf16x2(v0.z, v1.z), pack_bf16x2(v0.w, v1.w));
            *(uint4*)&sP[0][kp * SD2 + d4 * 4] = uv;
        }
    }
    __syncthreads();

    // ---- main loop ----
    for (int t = 0; t < TILES; ++t) {
        const int cur = t & 1;

        if (t + 1 < TILES) {
            const float4* src = (const float4*)(xb + (size_t)(t + 1) * KT * DIM);
#pragma unroll
            for (int r = 0; r < 4; ++r) {
                pv[2 * r]     = __ldg(src + (2 * krow + 8 * r) * 32 + d4);
                pv[2 * r + 1] = __ldg(src + (2 * krow + 8 * r + 1) * 32 + d4);
            }
        }

        // 2 k-steps of 16 over the packed tile
#pragma unroll
        for (int ks = 0; ks < 2; ++ks) {
            const uint32_t* base0 = &sP[cur][(ks * 8 + t4) * SD2];
            const uint32_t* base1 = &sP[cur][(ks * 8 + 4 + t4) * SD2];

            uint32_t bf[8][2];
#pragma unroll
            for (int nt = 0; nt < 8; ++nt) {
                bf[nt][0] = base0[wn + nt * 8 + g];
                bf[nt][1] = base1[wn + nt * 8 + g];
            }
#pragma unroll
            for (int mt = 0; mt < 4; ++mt) {
                const int m0 = wm + mt * 16;
                uint32_t a0 = base0[m0 + g];
                uint32_t a1 = base0[m0 + g + 8];
                uint32_t a2 = base1[m0 + g];
                uint32_t a3 = base1[m0 + g + 8];
#pragma unroll
                for (int nt = 0; nt < 8; ++nt)
                    mma_bf16(acc[mt][nt], a0, a1, a2, a3, bf[nt][0], bf[nt][1]);
            }
        }

        if (t + 1 < TILES) {
            const int nxt = (t + 1) & 1;
#pragma unroll
            for (int r = 0; r < 4; ++r) {
                const float4 v0 = pv[2 * r], v1 = pv[2 * r + 1];
                const float x00 = __shfl_sync(0xffffffffu, v0.x, 0);
                const float x01 = __shfl_sync(0xffffffffu, v1.x, 0);
                csum.x += v0.x + v1.x; csum.y += v0.y + v1.y;
                csum.z += v0.z + v1.z; csum.w += v0.w + v1.w;
                ksum.x = fmaf(v0.x, x00, fmaf(v1.x, x01, ksum.x));
                ksum.y = fmaf(v0.y, x00, fmaf(v1.y, x01, ksum.y));
                ksum.z = fmaf(v0.z, x00, fmaf(v1.z, x01, ksum.z));
                ksum.w = fmaf(v0.w, x00, fmaf(v1.w, x01, ksum.w));
                const int kp = krow + 4 * r;
                uint4 uv = make_uint4(pack_bf16x2(v0.x, v1.x), pack_bf16x2(v0.y, v1.y),
                                      pack_bf16x2(v0.z, v1.z), pack_bf16x2(v0.w, v1.w));
                *(uint4*)&sP[nxt][kp * SD2 + d4 * 4] = uv;
            }
        }
        __syncthreads();
    }

    // ---- column-sum + key reductions ----
    sCsum[tid] = csum;
    sKsum[tid] = ksum;
    __syncthreads();
    if (tid < 32) {
        float4 a = sCsum[tid];
        float4 k = sKsum[tid];
#pragma unroll
        for (int w = 1; w < 4; ++w) {
            float4 u = sCsum[tid + 32 * w];
            a.x += u.x; a.y += u.y; a.z += u.z; a.w += u.w;
            float4 q = sKsum[tid + 32 * w];
            k.x += q.x; k.y += q.y; k.z += q.z; k.w += q.w;
        }
        ((float4*)&g_sums[s][b][0])[tid] = a;
        ((float4*)&g_keyp[s][b][0])[tid] = k;
    }

    // ---- write partial cov (fp16) ----
    __half* outp = &g_covp[s][b][0][0];
#pragma unroll
    for (int mt = 0; mt < 4; ++mt) {
#pragma unroll
        for (int nt = 0; nt < 8; ++nt) {
            const int row = wm + mt * 16 + g;
            const int col = wn + nt * 8 + t4 * 2;
            *(__half2*)&outp[(size_t)row * DIM + col] =
                __float22half2_rn(make_float2(acc[mt][nt][0], acc[mt][nt][1]));
            *(__half2*)&outp[(size_t)(row + 8) * DIM + col] =
                __float22half2_rn(make_float2(acc[mt][nt][2], acc[mt][nt][3]));
        }
    }
}

// ---------------------------------------------------------------------------
// Kernel 2: fused finalize + scatter-sort (R13-proven, unchanged).
// ---------------------------------------------------------------------------
__global__ __launch_bounds__(256)
void finalize_scatter_kernel(float* __restrict__ out) {
    __shared__ float ssum[DIM];
    __shared__ float skey[DIM];
    __shared__ int   srank[16];

    const int b    = blockIdx.x >> 3;
    const int slab = blockIdx.x & 7;
    const int tid  = threadIdx.x;

    if (tid < DIM) {
        float sd = 0.f, kd = 0.f;
#pragma unroll
        for (int sp = 0; sp < SPLITS; ++sp) {
            sd += g_sums[sp][b][tid];
            kd += g_keyp[sp][b][tid];
        }
        ssum[tid] = sd;
        skey[tid] = kd;
    }
    __syncthreads();

    const float inv_n   = 1.0f / NPTS;
    const float inv_nm1 = 1.0f / (NPTS - 1);
    const float m0 = ssum[0] * inv_n;

    if (tid < DIM) {
        const float md = ssum[tid] * inv_n;
        float kv = (skey[tid] - (float)NPTS * md * m0) * inv_nm1;
        if (tid == 0) kv += LAM;
        skey[tid] = kv;
    }
    __syncthreads();

    if (tid < 16) {
        const int row = slab * 16 + tid;
        const float ki = skey[row];
        int r = 0;
        for (int j = 0; j < DIM; ++j) {
            const float kj = skey[j];
            if (kj < ki || (kj == ki && j < row)) ++r;
        }
        srank[tid] = r;
    }
    __syncthreads();

    float* ob = out + (size_t)b * (DIM * DIM);

#pragma unroll
    for (int r = 0; r < 2; ++r) {
        const int i = tid + 256 * r;
        const int dl = i >> 5;
        const int dd = slab * 16 + dl;
        const int e4 = i & 31;

        float4 acc = make_float4(0.f, 0.f, 0.f, 0.f);
#pragma unroll
        for (int sp = 0; sp < SPLITS; ++sp) {
            const __half2* p = (const __half2*)&g_covp[sp][b][dd][e4 * 4];
            float2 lo = __half22float2(p[0]);
            float2 hi = __half22float2(p[1]);
            acc.x += lo.x; acc.y += lo.y; acc.z += hi.x; acc.w += hi.y;
        }
        const float md = ssum[dd] * inv_n;
        const float4 se = *(const float4*)&ssum[e4 * 4];
        float4 o;
        o.x = (acc.x - (float)NPTS * md * (se.x * inv_n)) * inv_nm1;
        o.y = (acc.y - (float)NPTS * md * (se.y * inv_n)) * inv_nm1;
        o.z = (acc.z - (float)NPTS * md * (se.z * inv_n)) * inv_nm1;
        o.w = (acc.w - (float)NPTS * md * (se.w * inv_n)) * inv_nm1;
        const int e0 = e4 * 4;
        if (dd >= e0 && dd < e0 + 4) {
            if (dd == e0)     o.x += LAM;
            if (dd == e0 + 1) o.y += LAM;
            if (dd == e0 + 2) o.z += LAM;
            if (dd == e0 + 3) o.w += LAM;
        }
        if (e4 == 0) o.x = skey[dd];

        *(float4*)&ob[(size_t)srank[dl] * DIM + e4 * 4] = o;
    }
}

// ---------------------------------------------------------------------------
extern "C" void kernel_launch(void* const* d_in, const int* in_sizes, int n_in,
                              void* d_out, int out_size) {
    const float* x = (const float*)d_in[0];
    float* out = (float*)d_out;

    syrk_mma_kernel<<<BATCH * SPLITS, 128>>>(x);
    finalize_scatter_kernel<<<BATCH * 8, 256>>>(out);
}

// round 16
// speedup vs baseline: 1.4055x; 1.0506x over previous
#include <cuda_runtime.h>
#include <cuda_fp16.h>
#include <cstdint>

// Problem constants
#define BATCH 32
#define NPTS  8192
#define DIM   128
#define LAM   0.01f

// split-K SYRK config
#define SPLITS 8
#define KC     (NPTS / SPLITS)   // 1024 k-rows per CTA
#define KT     32                // k-rows per smem tile (16 bf16x2 pair-rows)
#define TILES  (KC / KT)         // 32
#define SD2    136               // packed smem row stride (uint32)

// Static device scratch (fp16 partials: 8 MB)
__device__ __half g_covp[SPLITS][BATCH][DIM][DIM];
__device__ float  g_sums[SPLITS][BATCH][DIM];
__device__ float  g_keyp[SPLITS][BATCH][DIM];      // exact fp32 dot(col_d, col_0)

// ---------------------------------------------------------------------------
// bf16 warp MMA m16n8k16 (full-rate HMMA.16816) — VERIFIED in R15.
// ---------------------------------------------------------------------------
__device__ __forceinline__ void mma_bf16(float c[4],
                                         uint32_t a0, uint32_t a1, uint32_t a2, uint32_t a3,
                                         uint32_t b0, uint32_t b1) {
    asm volatile(
        "mma.sync.aligned.m16n8k16.row.col.f32.bf16.bf16.f32 "
        "{%0,%1,%2,%3}, {%4,%5,%6,%7}, {%8,%9}, {%0,%1,%2,%3};"
        : "+f"(c[0]), "+f"(c[1]), "+f"(c[2]), "+f"(c[3])
        : "r"(a0), "r"(a1), "r"(a2), "r"(a3), "r"(b0), "r"(b1));
}

__device__ __forceinline__ uint32_t pack_bf16x2(float lo, float hi) {
    uint32_t u;
    asm("cvt.rn.bf16x2.f32 %0, %1, %2;" : "=r"(u) : "f"(hi), "f"(lo));
    return u;
}

// ---------------------------------------------------------------------------
// Kernel 1: split-K SYRK via bf16 mma.sync, 32x64 warp tiles, 256 threads.
// grid = BATCH*SPLITS, 8 warps/CTA, 2 CTAs/SM (16 warps resident).
// Warp w: rows (w&3)*32, cols (w>>2)*64.
// ---------------------------------------------------------------------------
__global__ __launch_bounds__(256, 2)
void syrk_mma_kernel(const float* __restrict__ x) {
    __shared__ uint32_t sP[2][(KT / 2) * SD2];   // 2 x 8704 B packed tiles
    __shared__ float4 sCsum[256];
    __shared__ float4 sKsum[256];

    const int bid = blockIdx.x;
    const int b = bid / SPLITS;
    const int s = bid % SPLITS;
    const float* __restrict__ xb = x + ((size_t)b * NPTS + (size_t)s * KC) * DIM;

    const int tid  = threadIdx.x;
    const int lane = tid & 31;
    const int wid  = tid >> 5;           // 0..7
    const int g    = lane >> 2;          // 0..7
    const int t4   = lane & 3;           // 0..3
    const int wm   = (wid & 3) * 32;     // warp M offset
    const int wn   = (wid >> 2) * 64;    // warp N offset
    const int d4   = tid & 31;           // fixed column group (4 cols)
    const int krow = tid >> 5;           // 0..7 base pair-row

    float4 csum = make_float4(0.f, 0.f, 0.f, 0.f);
    float4 ksum = make_float4(0.f, 0.f, 0.f, 0.f);
    float acc[2][8][4];
#pragma unroll
    for (int mt = 0; mt < 2; ++mt)
#pragma unroll
        for (int nt = 0; nt < 8; ++nt)
#pragma unroll
            for (int q = 0; q < 4; ++q) acc[mt][nt][q] = 0.f;

    float4 pv[4];   // 2 pair-rows x 2 rows x 4 cols per thread per tile

    // ---- prologue: load tile 0, accumulate, pack, store ----
    {
        const float4* src = (const float4*)xb;
#pragma unroll
        for (int r = 0; r < 2; ++r) {
            const int kp = krow + 8 * r;
            pv[2 * r]     = __ldg(src + (2 * kp) * 32 + d4);
            pv[2 * r + 1] = __ldg(src + (2 * kp + 1) * 32 + d4);
        }
#pragma unroll
        for (int r = 0; r < 2; ++r) {
            const float4 v0 = pv[2 * r], v1 = pv[2 * r + 1];
            const float x00 = __shfl_sync(0xffffffffu, v0.x, 0);
            const float x01 = __shfl_sync(0xffffffffu, v1.x, 0);
            csum.x += v0.x + v1.x; csum.y += v0.y + v1.y;
            csum.z += v0.z + v1.z; csum.w += v0.w + v1.w;
            ksum.x = fmaf(v0.x, x00, fmaf(v1.x, x01, ksum.x));
            ksum.y = fmaf(v0.y, x00, fmaf(v1.y, x01, ksum.y));
            ksum.z = fmaf(v0.z, x00, fmaf(v1.z, x01, ksum.z));
            ksum.w = fmaf(v0.w, x00, fmaf(v1.w, x01, ksum.w));
            const int kp = krow + 8 * r;
            uint4 uv = make_uint4(pack_bf16x2(v0.x, v1.x), pack_bf16x2(v0.y, v1.y),
                                  pack_bf16x2(v0.z, v1.z), pack_bf16x2(v0.w, v1.w));
            *(uint4*)&sP[0][kp * SD2 + d4 * 4] = uv;
        }
    }
    __syncthreads();

    // ---- main loop ----
    for (int t = 0; t < TILES; ++t) {
        const int cur = t & 1;

        if (t + 1 < TILES) {
            const float4* src = (const float4*)(xb + (size_t)(t + 1) * KT * DIM);
#pragma unroll
            for (int r = 0; r < 2; ++r) {
                const int kp = krow + 8 * r;
                pv[2 * r]     = __ldg(src + (2 * kp) * 32 + d4);
                pv[2 * r + 1] = __ldg(src + (2 * kp + 1) * 32 + d4);
            }
        }

        // 2 k-steps of 16 over the packed tile
#pragma unroll
        for (int ks = 0; ks < 2; ++ks) {
            const uint32_t* base0 = &sP[cur][(ks * 8 + t4) * SD2];
            const uint32_t* base1 = &sP[cur][(ks * 8 + 4 + t4) * SD2];

            uint32_t bf[8][2];
#pragma unroll
            for (int nt = 0; nt < 8; ++nt) {
                bf[nt][0] = base0[wn + nt * 8 + g];
                bf[nt][1] = base1[wn + nt * 8 + g];
            }
#pragma unroll
            for (int mt = 0; mt < 2; ++mt) {
                const int m0 = wm + mt * 16;
                uint32_t a0 = base0[m0 + g];
                uint32_t a1 = base0[m0 + g + 8];
                uint32_t a2 = base1[m0 + g];
                uint32_t a3 = base1[m0 + g + 8];
#pragma unroll
                for (int nt = 0; nt < 8; ++nt)
                    mma_bf16(acc[mt][nt], a0, a1, a2, a3, bf[nt][0], bf[nt][1]);
            }
        }

        if (t + 1 < TILES) {
            const int nxt = (t + 1) & 1;
#pragma unroll
            for (int r = 0; r < 2; ++r) {
                const float4 v0 = pv[2 * r], v1 = pv[2 * r + 1];
                const float x00 = __shfl_sync(0xffffffffu, v0.x, 0);
                const float x01 = __shfl_sync(0xffffffffu, v1.x, 0);
                csum.x += v0.x + v1.x; csum.y += v0.y + v1.y;
                csum.z += v0.z + v1.z; csum.w += v0.w + v1.w;
                ksum.x = fmaf(v0.x, x00, fmaf(v1.x, x01, ksum.x));
                ksum.y = fmaf(v0.y, x00, fmaf(v1.y, x01, ksum.y));
                ksum.z = fmaf(v0.z, x00, fmaf(v1.z, x01, ksum.z));
                ksum.w = fmaf(v0.w, x00, fmaf(v1.w, x01, ksum.w));
                const int kp = krow + 8 * r;
                uint4 uv = make_uint4(pack_bf16x2(v0.x, v1.x), pack_bf16x2(v0.y, v1.y),
                                      pack_bf16x2(v0.z, v1.z), pack_bf16x2(v0.w, v1.w));
                *(uint4*)&sP[nxt][kp * SD2 + d4 * 4] = uv;
            }
        }
        __syncthreads();
    }

    // ---- column-sum + key reductions (8 warps) ----
    sCsum[tid] = csum;
    sKsum[tid] = ksum;
    __syncthreads();
    if (tid < 32) {
        float4 a = sCsum[tid];
        float4 k = sKsum[tid];
#pragma unroll
        for (int w = 1; w < 8; ++w) {
            float4 u = sCsum[tid + 32 * w];
            a.x += u.x; a.y += u.y; a.z += u.z; a.w += u.w;
            float4 q = sKsum[tid + 32 * w];
            k.x += q.x; k.y += q.y; k.z += q.z; k.w += q.w;
        }
        ((float4*)&g_sums[s][b][0])[tid] = a;
        ((float4*)&g_keyp[s][b][0])[tid] = k;
    }

    // ---- write partial cov (fp16) ----
    __half* outp = &g_covp[s][b][0][0];
#pragma unroll
    for (int mt = 0; mt < 2; ++mt) {
#pragma unroll
        for (int nt = 0; nt < 8; ++nt) {
            const int row = wm + mt * 16 + g;
            const int col = wn + nt * 8 + t4 * 2;
            *(__half2*)&outp[(size_t)row * DIM + col] =
                __float22half2_rn(make_float2(acc[mt][nt][0], acc[mt][nt][1]));
            *(__half2*)&outp[(size_t)(row + 8) * DIM + col] =
                __float22half2_rn(make_float2(acc[mt][nt][2], acc[mt][nt][3]));
        }
    }
}

// ---------------------------------------------------------------------------
// Kernel 2: fused finalize + scatter-sort. 512 CTAs (batch x 8-row slab),
// 256 threads, 1 float4 slot per thread.
// ---------------------------------------------------------------------------
__global__ __launch_bounds__(256)
void finalize_scatter_kernel(float* __restrict__ out) {
    __shared__ float ssum[DIM];
    __shared__ float skey[DIM];
    __shared__ int   srank[8];

    const int b    = blockIdx.x >> 4;
    const int slab = blockIdx.x & 15;    // rows slab*8 .. +8
    const int tid  = threadIdx.x;

    if (tid < DIM) {
        float sd = 0.f, kd = 0.f;
#pragma unroll
        for (int sp = 0; sp < SPLITS; ++sp) {
            sd += g_sums[sp][b][tid];
            kd += g_keyp[sp][b][tid];
        }
        ssum[tid] = sd;
        skey[tid] = kd;
    }
    __syncthreads();

    const float inv_n   = 1.0f / NPTS;
    const float inv_nm1 = 1.0f / (NPTS - 1);
    const float m0 = ssum[0] * inv_n;

    if (tid < DIM) {
        const float md = ssum[tid] * inv_n;
        float kv = (skey[tid] - (float)NPTS * md * m0) * inv_nm1;
        if (tid == 0) kv += LAM;
        skey[tid] = kv;
    }
    __syncthreads();

    if (tid < 8) {
        const int row = slab * 8 + tid;
        const float ki = skey[row];
        int r = 0;
        for (int j = 0; j < DIM; ++j) {
            const float kj = skey[j];
            if (kj < ki || (kj == ki && j < row)) ++r;
        }
        srank[tid] = r;
    }
    __syncthreads();

    float* ob = out + (size_t)b * (DIM * DIM);

    const int dl = tid >> 5;             // 0..7
    const int dd = slab * 8 + dl;
    const int e4 = tid & 31;

    float4 acc = make_float4(0.f, 0.f, 0.f, 0.f);
#pragma unroll
    for (int sp = 0; sp < SPLITS; ++sp) {
        const __half2* p = (const __half2*)&g_covp[sp][b][dd][e4 * 4];
        float2 lo = __half22float2(p[0]);
        float2 hi = __half22float2(p[1]);
        acc.x += lo.x; acc.y += lo.y; acc.z += hi.x; acc.w += hi.y;
    }
    const float md = ssum[dd] * inv_n;
    const float4 se = *(const float4*)&ssum[e4 * 4];
    float4 o;
    o.x = (acc.x - (float)NPTS * md * (se.x * inv_n)) * inv_nm1;
    o.y = (acc.y - (float)NPTS * md * (se.y * inv_n)) * inv_nm1;
    o.z = (acc.z - (float)NPTS * md * (se.z * inv_n)) * inv_nm1;
    o.w = (acc.w - (float)NPTS * md * (se.w * inv_n)) * inv_nm1;
    const int e0 = e4 * 4;
    if (dd >= e0 && dd < e0 + 4) {
        if (dd == e0)     o.x += LAM;
        if (dd == e0 + 1) o.y += LAM;
        if (dd == e0 + 2) o.z += LAM;
        if (dd == e0 + 3) o.w += LAM;
    }
    if (e4 == 0) o.x = skey[dd];

    *(float4*)&ob[(size_t)srank[dl] * DIM + e4 * 4] = o;
}

// ---------------------------------------------------------------------------
extern "C" void kernel_launch(void* const* d_in, const int* in_sizes, int n_in,
                              void* d_out, int out_size) {
    const float* x = (const float*)d_in[0];
    float* out = (float*)d_out;

    syrk_mma_kernel<<<BATCH * SPLITS, 256>>>(x);
    finalize_scatter_kernel<<<BATCH * 16, 256>>>(out);
}